// round 3
// baseline (speedup 1.0000x reference)
#include <cuda_runtime.h>
#include <cstdint>
#include <cstddef>

#define D_DIM 2048
#define NEXP  64
#define TOPK  8

// Fused MoE gate: logits GEMM (64 rows x 64 experts per block, K-tiled by 64)
// + softmax + exact top-8 + renormalize, one kernel.
__global__ __launch_bounds__(128) void moe_gate_kernel(
    const float* __restrict__ r, const float* __restrict__ W,
    const float* __restrict__ bias, float* __restrict__ out,
    size_t soft_base)
{
    __shared__ float rs[64][65];   // r tile [row][k], pad 65 -> conflict-free a-broadcasts
    __shared__ float ws[64][64];   // W tile transposed [k][expert], LDS.128-friendly

    const int tid = threadIdx.x;
    const int tx  = tid & 7;       // expert group: experts tx*8 .. tx*8+7
    const int ty  = tid >> 3;      // row group:    rows   ty*4 .. ty*4+3
    const int row0 = blockIdx.x * 64;

    float acc[4][8];
#pragma unroll
    for (int i = 0; i < 4; i++)
#pragma unroll
        for (int j = 0; j < 8; j++) acc[i][j] = 0.f;

    const int kq = tid & 15;   // r-load: float4 column group
    const int rq = tid >> 4;   // r-load: row sub (0..7)
    const int we = tid & 63;   // W-load: expert
    const int wk = tid >> 6;   // W-load: k phase (0..1)

    for (int k0 = 0; k0 < D_DIM; k0 += 64) {
        __syncthreads();
        // ---- load r tile: rows 64 x k 64 (coalesced float4, 2-way STS ok)
        const float* rp = r + (size_t)row0 * D_DIM + k0 + kq * 4;
#pragma unroll
        for (int p = 0; p < 8; p++) {
            int row = rq + p * 8;
            float4 v = *(const float4*)(rp + (size_t)row * D_DIM);
            rs[row][kq * 4 + 0] = v.x; rs[row][kq * 4 + 1] = v.y;
            rs[row][kq * 4 + 2] = v.z; rs[row][kq * 4 + 3] = v.w;
        }
        // ---- load W tile transposed: ws[k][e] from W[e][k0+k]
        // (per-lane strided global reads are L1-line-reused; STS conflict-free: bank = e)
        const float* wp = W + (size_t)we * D_DIM + k0;
#pragma unroll
        for (int p = 0; p < 8; p++) {
            int kg = (wk + p * 2) * 4;
            float4 v = *(const float4*)(wp + kg);
            ws[kg + 0][we] = v.x; ws[kg + 1][we] = v.y;
            ws[kg + 2][we] = v.z; ws[kg + 3][we] = v.w;
        }
        __syncthreads();
        // ---- FMA-bound inner loop: 32 FFMA per kk per thread, 6 LDS
#pragma unroll 8
        for (int kk = 0; kk < 64; kk++) {
            float4 w0 = *(const float4*)&ws[kk][tx * 8];
            float4 w1 = *(const float4*)&ws[kk][tx * 8 + 4];
            float wv[8] = {w0.x, w0.y, w0.z, w0.w, w1.x, w1.y, w1.z, w1.w};
            float av[4];
#pragma unroll
            for (int i = 0; i < 4; i++) av[i] = rs[ty * 4 + i][kk];
#pragma unroll
            for (int i = 0; i < 4; i++)
#pragma unroll
                for (int j = 0; j < 8; j++)
                    acc[i][j] = fmaf(av[i], wv[j], acc[i][j]);
        }
    }
    __syncthreads();

    // ---- epilogue: logits (+bias) into rs (reused as logit[64][65])
    float bj[8];
#pragma unroll
    for (int j = 0; j < 8; j++) bj[j] = bias[tx * 8 + j];
#pragma unroll
    for (int i = 0; i < 4; i++)
#pragma unroll
        for (int j = 0; j < 8; j++)
            rs[ty * 4 + i][tx * 8 + j] = acc[i][j] + bj[j];
    float* hsm = &ws[0][0];   // reuse ws as hard-weights staging [64][64]
    __syncthreads();

    if (tid < 64) {
        const int row = tid;
        float mx = -3.4e38f;
#pragma unroll 8
        for (int c = 0; c < NEXP; c++) mx = fmaxf(mx, rs[row][c]);
        float s = 0.f;
#pragma unroll 8
        for (int c = 0; c < NEXP; c++) s += __expf(rs[row][c] - mx);

        // exact top-8 on logits (monotonic with softmax); stable lowest-index
        // tie-break to match lax.top_k
        unsigned long long msk = 0ull;
        float selexp = 0.f;
        for (int it = 0; it < TOPK; it++) {
            float best = -3.4e38f; int bi = 0;
            for (int c = 0; c < NEXP; c++) {
                float v = rs[row][c];
                bool freec = ((msk >> c) & 1ull) == 0ull;
                if (freec && v > best) { best = v; bi = c; }
            }
            msk |= (1ull << bi);
            selexp += __expf(best - mx);
        }
        float inv_s = 1.f / s;
        float denom = selexp * inv_s + 1e-9f;   // reference's +1e-9
        float inv_d = 1.f / denom;
#pragma unroll 8
        for (int c = 0; c < NEXP; c++) {
            float e    = __expf(rs[row][c] - mx);
            float soft = e * inv_s;
            hsm[row * 64 + c] = ((msk >> c) & 1ull) ? soft * inv_d : 0.f;
            rs[row][c] = soft;
        }
    }
    __syncthreads();

    // ---- coalesced float4 write-out: hard at [0, B*E), soft at [soft_base, ...)
#pragma unroll
    for (int p = 0; p < 8; p++) {
        int idx = tid + p * 128;           // 0..1023 float4 slots over 64x64
        int row = idx >> 4;
        int c4  = (idx & 15) << 2;
        float4 hv = *(const float4*)&hsm[row * 64 + c4];
        float4 sv = make_float4(rs[row][c4], rs[row][c4 + 1],
                                rs[row][c4 + 2], rs[row][c4 + 3]);
        size_t g = (size_t)(row0 + row) * NEXP + c4;
        *(float4*)&out[g]             = hv;
        *(float4*)&out[soft_base + g] = sv;
    }
}

extern "C" void kernel_launch(void* const* d_in, const int* in_sizes, int n_in,
                              void* d_out, int out_size)
{
    const float* r = (const float*)d_in[0];   // (B, 2048) fp32
    const float* W = (const float*)d_in[1];   // (64, 2048) fp32
    const float* b = (const float*)d_in[2];   // (64,) fp32
    float* out = (float*)d_out;               // [hard | soft], each B*64 fp32

    int B = in_sizes[0] / D_DIM;              // 32768
    size_t soft_base = (size_t)out_size / 2;  // tuple flattening: hard first

    moe_gate_kernel<<<B / 64, 128>>>(r, W, b, out, soft_base);
}

// round 9
// speedup vs baseline: 1.3174x; 1.3174x over previous
#include <cuda_runtime.h>
#include <cstdint>
#include <cstddef>

#define D_DIM  2048
#define NEXP   64
#define TILE_M 128
#define KC     32
#define NCH    (D_DIM / KC)   // 64 chunks
#define NTHR   128
#define MARGIN 2e-4f
#define MAXC   16

// ---- smem layout (bytes). Row stride 144B = 36 floats -> conflict-free frags.
#define A_OFF    0             // 3 stages x 128 rows x 144B
#define A_STG    18432
#define BH_OFF   55296         // 3 stages x 64 rows x 144B
#define B_STG    9216
#define BL_OFF   82944
#define BIAS_OFF 110592
#define SMEM_TOTAL 110848
#define LG_PAD   66            // epilogue logits row pad (floats)

__device__ float g_Whf[NEXP * D_DIM];   // tf32-valued hi part of W
__device__ float g_Wlf[NEXP * D_DIM];   // tf32-valued lo part of W

// ---------------- helpers ----------------
__device__ __forceinline__ uint32_t smem_u32(const void* p) {
    uint32_t a;
    asm("{ .reg .u64 t; cvta.to.shared.u64 t, %1; cvt.u32.u64 %0, t; }" : "=r"(a) : "l"(p));
    return a;
}
__device__ __forceinline__ void cpa16(void* dst, const void* src) {
    asm volatile("cp.async.cg.shared.global [%0], [%1], 16;"
                 :: "r"(smem_u32(dst)), "l"(src) : "memory");
}
#define CP_COMMIT() asm volatile("cp.async.commit_group;" ::: "memory")
#define CP_WAIT(n)  asm volatile("cp.async.wait_group %0;" :: "n"(n) : "memory")

__device__ __forceinline__ uint32_t f2tf32(float x) {
    uint32_t u;
    asm("cvt.rna.tf32.f32 %0, %1;" : "=r"(u) : "f"(x));
    return u;
}
__device__ __forceinline__ void tfsplit(float x, uint32_t& h, uint32_t& l) {
    h = f2tf32(x);
    l = f2tf32(x - __uint_as_float(h));   // residual subtraction is exact
}
__device__ __forceinline__ void mma_tf32(float* c, const uint32_t* a, uint32_t b0, uint32_t b1) {
    asm volatile("mma.sync.aligned.m16n8k8.row.col.f32.tf32.tf32.f32 "
        "{%0,%1,%2,%3}, {%4,%5,%6,%7}, {%8,%9}, {%0,%1,%2,%3};"
        : "+f"(c[0]), "+f"(c[1]), "+f"(c[2]), "+f"(c[3])
        : "r"(a[0]), "r"(a[1]), "r"(a[2]), "r"(a[3]), "r"(b0), "r"(b1));
}

// ---------------- W pre-split (tf32 hi/lo) ----------------
__global__ void conv_w_kernel(const float* __restrict__ W) {
    int i = blockIdx.x * 256 + threadIdx.x;
    uint32_t h, l;
    tfsplit(W[i], h, l);
    g_Whf[i] = __uint_as_float(h);
    g_Wlf[i] = __uint_as_float(l);
}

// ---------------- main fused kernel ----------------
__global__ __launch_bounds__(NTHR, 2)
void moe_gate_mma(const float* __restrict__ r, const float* __restrict__ W,
                  const float* __restrict__ bias,
                  float* __restrict__ out, size_t soft_base)
{
    extern __shared__ char smem[];
    const int tid  = threadIdx.x;
    const int warp = tid >> 5, lane = tid & 31;
    const int g    = lane >> 2, tg = lane & 3;
    const int row0 = blockIdx.x * TILE_M;

    if (tid < NEXP) *(float*)(smem + BIAS_OFF + tid * 4) = bias[tid];

    // ---- cp.async issue for one chunk into stage ci%3
    auto issue = [&](int ci) {
        const int s  = ci % 3;
        const int k0 = ci * KC;
#pragma unroll
        for (int i = 0; i < 8; i++) {                 // A: 128 rows x 8 x 16B
            int id = tid + i * NTHR;
            int row = id >> 3, seg = id & 7;
            cpa16(smem + A_OFF + s * A_STG + row * 144 + seg * 16,
                  r + (size_t)(row0 + row) * D_DIM + k0 + seg * 4);
        }
#pragma unroll
        for (int i = 0; i < 4; i++) {                 // B hi/lo: 64 rows x 8 x 16B each
            int id = tid + i * NTHR;
            int e = id >> 3, seg = id & 7;
            cpa16(smem + BH_OFF + s * B_STG + e * 144 + seg * 16,
                  g_Whf + (size_t)e * D_DIM + k0 + seg * 4);
            cpa16(smem + BL_OFF + s * B_STG + e * 144 + seg * 16,
                  g_Wlf + (size_t)e * D_DIM + k0 + seg * 4);
        }
        CP_COMMIT();
    };

    issue(0);
    issue(1);

    float c[2][8][4];
#pragma unroll
    for (int mt = 0; mt < 2; mt++)
#pragma unroll
        for (int nt = 0; nt < 8; nt++)
#pragma unroll
            for (int j = 0; j < 4; j++) c[mt][nt][j] = 0.f;

    for (int ci = 0; ci < NCH; ci++) {
        const int s = ci % 3;
        if (ci == NCH - 1) { CP_WAIT(0); } else { CP_WAIT(1); }
        __syncthreads();   // chunk ci landed; all warps done reading stage (ci+2)%3

        if (ci + 2 < NCH) issue(ci + 2);

        const char* As = smem + A_OFF + s * A_STG;
        const char* Bh = smem + BH_OFF + s * B_STG;
        const char* Bl = smem + BL_OFF + s * B_STG;

#pragma unroll
        for (int ks = 0; ks < 4; ks++) {
            // ---- A frags: load fp32, split to tf32 hi/lo in registers
            uint32_t ahi[2][4], alo[2][4];
#pragma unroll
            for (int mt = 0; mt < 2; mt++) {
                const float* ap = (const float*)(As + (warp * 32 + mt * 16 + g) * 144)
                                  + ks * 8 + tg;
                float a0 = ap[0];
                float a1 = ap[8 * 36];
                float a2 = ap[4];
                float a3 = ap[8 * 36 + 4];
                tfsplit(a0, ahi[mt][0], alo[mt][0]);
                tfsplit(a1, ahi[mt][1], alo[mt][1]);
                tfsplit(a2, ahi[mt][2], alo[mt][2]);
                tfsplit(a3, ahi[mt][3], alo[mt][3]);
            }
#pragma unroll
            for (int nt = 0; nt < 8; nt++) {
                const uint32_t* bhp = (const uint32_t*)(Bh + (nt * 8 + g) * 144) + ks * 8 + tg;
                const uint32_t* blp = (const uint32_t*)(Bl + (nt * 8 + g) * 144) + ks * 8 + tg;
                uint32_t bh0 = bhp[0], bh1 = bhp[4];
                uint32_t bl0 = blp[0], bl1 = blp[4];
#pragma unroll
                for (int mt = 0; mt < 2; mt++) {
                    mma_tf32(c[mt][nt], ahi[mt], bh0, bh1);   // hi*hi
                    mma_tf32(c[mt][nt], ahi[mt], bl0, bl1);   // hi*lo
                    mma_tf32(c[mt][nt], alo[mt], bh0, bh1);   // lo*hi
                }
            }
        }
    }
    __syncthreads();   // all MMAs done; smem A region free for logits staging

    // ---- scatter C frags to per-warp logits[32][LG_PAD]
    float* lg = (float*)(smem + warp * (32 * LG_PAD * 4));
#pragma unroll
    for (int mt = 0; mt < 2; mt++)
#pragma unroll
        for (int nt = 0; nt < 8; nt++) {
            int rr = mt * 16 + g, cc = nt * 8 + tg * 2;
            *(float2*)&lg[rr * LG_PAD + cc]       = make_float2(c[mt][nt][0], c[mt][nt][1]);
            *(float2*)&lg[(rr + 8) * LG_PAD + cc] = make_float2(c[mt][nt][2], c[mt][nt][3]);
        }
    __syncwarp();

    // ---- per-row softmax + top-8 (lane = row within warp)
    const float* bs = (const float*)(smem + BIAS_OFF);
    const int myrow = row0 + warp * 32 + lane;
    float v[64];
#pragma unroll
    for (int cc = 0; cc < NEXP; cc++) v[cc] = lg[lane * LG_PAD + cc] + bs[cc];

    float mx = -3.4e38f;
#pragma unroll
    for (int cc = 0; cc < NEXP; cc++) mx = fmaxf(mx, v[cc]);
    float ssum = 0.f;
#pragma unroll
    for (int cc = 0; cc < NEXP; cc++) ssum += __expf(v[cc] - mx);

    // top-9 sorted insert (need 8th AND 9th for the margin test)
    float t[9];
#pragma unroll
    for (int j = 0; j < 9; j++) t[j] = -3.4e38f;
#pragma unroll
    for (int cc = 0; cc < NEXP; cc++) {
        float x = v[cc];
#pragma unroll
        for (int j = 0; j < 9; j++) {
            float hi = fmaxf(t[j], x), lo = fminf(t[j], x);
            t[j] = hi; x = lo;
        }
    }
    float thr = t[7];
    unsigned long long msk = 0ull;

    if (thr - t[8] >= MARGIN) {
        // ---- unambiguous: noisy selection is provably correct
        int cnt_gt = 0;
#pragma unroll
        for (int cc = 0; cc < NEXP; cc++) cnt_gt += (v[cc] > thr) ? 1 : 0;
        int quota = 8 - cnt_gt, eq = 0;
#pragma unroll
        for (int cc = 0; cc < NEXP; cc++) {
            bool sg = v[cc] > thr;
            bool se = (v[cc] == thr) && (eq < quota);
            if (se) eq++;
            if (sg || se) msk |= 1ull << cc;
        }
    } else {
        // ---- ambiguous boundary (~0.5% of rows): exact fp32 recompute of
        // candidate experts, select top-8 from exact values.
        int   cidx[MAXC];
        float cval[MAXC];
        int nc = 0;
        float lim = thr - MARGIN;
        for (int cc = 0; cc < NEXP; cc++)
            if (v[cc] >= lim && nc < MAXC) { cidx[nc++] = cc; }

        const float* rrow = r + (size_t)myrow * D_DIM;
        for (int j = 0; j < nc; j++) {
            const float* wrow = W + (size_t)cidx[j] * D_DIM;
            float s0 = 0.f, s1 = 0.f, s2 = 0.f, s3 = 0.f;
            for (int k = 0; k < D_DIM; k += 4) {
                float4 a = *(const float4*)(rrow + k);
                float4 w = *(const float4*)(wrow + k);
                s0 = fmaf(a.x, w.x, s0); s1 = fmaf(a.y, w.y, s1);
                s2 = fmaf(a.z, w.z, s2); s3 = fmaf(a.w, w.w, s3);
            }
            cval[j] = (s0 + s1) + (s2 + s3) + bs[cidx[j]];
        }
        // top-8 among candidates, lowest-index tie-break (strict >)
        for (int it = 0; it < 8; it++) {
            float best = -3.4e38f; int bj = 0;
            for (int j = 0; j < nc; j++) {
                bool freej = ((msk >> cidx[j]) & 1ull) == 0ull;
                if (freej && cval[j] > best) { best = cval[j]; bj = j; }
            }
            msk |= 1ull << cidx[bj];
        }
    }

    float selexp = 0.f;
#pragma unroll
    for (int cc = 0; cc < NEXP; cc++)
        if ((msk >> cc) & 1ull) selexp += __expf(v[cc] - mx);

    float inv_s = 1.0f / ssum;
    float inv_d = 1.0f / (selexp * inv_s + 1e-9f);

    const size_t gr = (size_t)myrow * NEXP;
#pragma unroll
    for (int c4 = 0; c4 < NEXP; c4 += 4) {
        float sf[4], hd[4];
#pragma unroll
        for (int j = 0; j < 4; j++) {
            float soft = __expf(v[c4 + j] - mx) * inv_s;
            sf[j] = soft;
            hd[j] = ((msk >> (c4 + j)) & 1ull) ? soft * inv_d : 0.f;
        }
        *(float4*)(out + gr + c4)             = make_float4(hd[0], hd[1], hd[2], hd[3]);
        *(float4*)(out + soft_base + gr + c4) = make_float4(sf[0], sf[1], sf[2], sf[3]);
    }
}

extern "C" void kernel_launch(void* const* d_in, const int* in_sizes, int n_in,
                              void* d_out, int out_size)
{
    const float* r = (const float*)d_in[0];   // (B, 2048) fp32
    const float* W = (const float*)d_in[1];   // (64, 2048) fp32
    const float* b = (const float*)d_in[2];   // (64,) fp32
    float* out = (float*)d_out;               // [hard | soft]

    int B = in_sizes[0] / D_DIM;              // 32768
    size_t soft_base = (size_t)out_size / 2;

    cudaFuncSetAttribute(moe_gate_mma, cudaFuncAttributeMaxDynamicSharedMemorySize, SMEM_TOTAL);

    conv_w_kernel<<<(NEXP * D_DIM) / 256, 256>>>(W);
    moe_gate_mma<<<B / TILE_M, NTHR, SMEM_TOTAL>>>(r, W, b, out, soft_base);
}